// round 15
// baseline (speedup 1.0000x reference)
#include <cuda_runtime.h>
#include <math.h>

#define KSTREAMS 8
#define DDIM 128
#define WARPS_PER_BLOCK 16
#define THREADS (WARPS_PER_BLOCK * 32)
#define ITERS 2   // samples per warp; grid = B / (WARPS_PER_BLOCK * ITERS)

// Device-global accumulators (allocation-free scratch per harness rules).
// Zero at module load; finalize kernel resets them after consuming, so every
// graph replay sees identical initial state.
__device__ double g_loss_sum;
__device__ double g_cnt;

__global__ __launch_bounds__(THREADS, 4) void sl_main_kernel(
    const float4* __restrict__ emb4,   // [K, B, 32] as float4
    const int*    __restrict__ target, // [K, B]
    int B)
{
    const int warp_in_block = threadIdx.x >> 5;
    const int lane = threadIdx.x & 31;
    const size_t stream_stride = (size_t)B * 32;

    float loss_acc = 0.0f;
    float inc_acc  = 0.0f;

    // Each iteration, the block covers a contiguous 16-sample span:
    // b = blockBase + iter*WPB + warp  (consecutive warps -> consecutive b)
    const int block_base = blockIdx.x * (WARPS_PER_BLOCK * ITERS);

    #pragma unroll
    for (int it = 0; it < ITERS; it++) {
        const int b = block_base + it * WARPS_PER_BLOCK + warp_in_block;
        if (b >= B) break;

        const size_t row = (size_t)b * 32 + lane;

        // Anchor chunk + all 7 peer chunks; streaming (evict-first) loads —
        // this data is touched exactly once.
        float4 a = __ldcs(&emb4[row]);
        float4 e[KSTREAMS - 1];
        #pragma unroll
        for (int k = 1; k < KSTREAMS; k++) {
            e[k - 1] = __ldcs(&emb4[row + (size_t)k * stream_stride]);
        }

        float d[KSTREAMS - 1];
        #pragma unroll
        for (int k = 0; k < KSTREAMS - 1; k++) {
            float dx = a.x - e[k].x;
            float dy = a.y - e[k].y;
            float dz = a.z - e[k].z;
            float dw = a.w - e[k].w;
            d[k] = dx * dx + dy * dy + dz * dz + dw * dw;
        }

        // 7 simultaneous warp butterfly reductions
        #pragma unroll
        for (int off = 16; off > 0; off >>= 1) {
            #pragma unroll
            for (int k = 0; k < KSTREAMS - 1; k++) {
                d[k] += __shfl_xor_sync(0xffffffffu, d[k], off);
            }
        }

        // Targets: lane k (k < 8) loads target[k, b]; broadcast via shfl
        int t = 0;
        if (lane < KSTREAMS) t = target[(size_t)lane * B + b];
        const int t0 = __shfl_sync(0xffffffffu, t, 0);

        // Pack same-flags into a bitmask (register-lean)
        unsigned int same_mask = 0u;
        float mmax = -INFINITY;
        float same_sum = 0.0f;
        #pragma unroll
        for (int k = 1; k < KSTREAMS; k++) {
            int tk = __shfl_sync(0xffffffffu, t, k);
            if (tk == t0) {
                same_mask |= (1u << (k - 1));
                mmax = fmaxf(mmax, d[k - 1]);
                same_sum += d[k - 1];
            }
        }

        const bool  any_same = (same_mask != 0u);
        const float alpha = any_same ? mmax : 1.0f;

        float neg_sum = 0.0f;
        bool  any_neg = false;
        #pragma unroll
        for (int k = 0; k < KSTREAMS - 1; k++) {
            float margin = d[k] - alpha;
            if (!((same_mask >> k) & 1u) && margin < 0.0f) {
                neg_sum += margin;
                any_neg = true;
            }
        }

        if (any_same || any_neg) {
            loss_acc += same_sum - neg_sum;
            inc_acc  += 1.0f;
        }
    }

    // Block reduction of per-warp (lane-0) accumulators
    __shared__ float s_loss[WARPS_PER_BLOCK];
    __shared__ float s_inc[WARPS_PER_BLOCK];
    if (lane == 0) {
        s_loss[warp_in_block] = loss_acc;
        s_inc[warp_in_block]  = inc_acc;
    }
    __syncthreads();

    if (warp_in_block == 0) {
        float vl = (lane < WARPS_PER_BLOCK) ? s_loss[lane] : 0.0f;
        float vi = (lane < WARPS_PER_BLOCK) ? s_inc[lane]  : 0.0f;
        #pragma unroll
        for (int off = 16; off > 0; off >>= 1) {
            vl += __shfl_xor_sync(0xffffffffu, vl, off);
            vi += __shfl_xor_sync(0xffffffffu, vi, off);
        }
        if (lane == 0) {
            atomicAdd(&g_loss_sum, (double)vl);
            atomicAdd(&g_cnt, (double)vi);
        }
    }

    // PDL trigger: releases the dependent finalize grid's sync once all
    // blocks reach here; prior memory ops are visible to the dependent grid.
    cudaTriggerProgrammaticLaunchCompletion();
}

// Finalize via PDL: launched overlapping the main kernel; the grid-dependency
// sync waits (in hardware) until all primary blocks have triggered and makes
// their writes visible. Consumes totals, writes output, resets accumulators.
__global__ void sl_finalize_kernel(float* __restrict__ out) {
    cudaGridDependencySynchronize();
    double total = g_loss_sum;
    double cnt   = g_cnt;
    if (cnt < 1.0) cnt = 1.0;
    out[0] = (float)(total / cnt);
    g_loss_sum = 0.0;
    g_cnt      = 0.0;
}

extern "C" void kernel_launch(void* const* d_in, const int* in_sizes, int n_in,
                              void* d_out, int out_size) {
    const float* embeddings = (const float*)d_in[0];  // [K, B, D] f32
    const int*   target     = (const int*)d_in[1];    // [K, B] i32
    float* out = (float*)d_out;

    const int B = in_sizes[0] / (KSTREAMS * DDIM);
    const int samples_per_block = WARPS_PER_BLOCK * ITERS;
    const int grid = (B + samples_per_block - 1) / samples_per_block;

    sl_main_kernel<<<grid, THREADS>>>((const float4*)embeddings, target, B);

    // PDL launch of finalize: overlaps its launch latency with the main kernel.
    cudaLaunchConfig_t cfg = {};
    cfg.gridDim  = dim3(1, 1, 1);
    cfg.blockDim = dim3(1, 1, 1);
    cfg.dynamicSmemBytes = 0;
    cfg.stream = 0;  // legacy default stream (the capture stream)
    cudaLaunchAttribute attrs[1];
    attrs[0].id = cudaLaunchAttributeProgrammaticStreamSerialization;
    attrs[0].val.programmaticStreamSerializationAllowed = 1;
    cfg.attrs = attrs;
    cfg.numAttrs = 1;
    cudaLaunchKernelEx(&cfg, sl_finalize_kernel, out);
}

// round 17
// speedup vs baseline: 1.0588x; 1.0588x over previous
#include <cuda_runtime.h>
#include <math.h>

#define KSTREAMS 8
#define DDIM 128
#define WARPS_PER_BLOCK 8
#define THREADS (WARPS_PER_BLOCK * 32)

// Device-global accumulators (allocation-free scratch per harness rules).
// Zero at module load; finalize kernel resets them after consuming, so every
// graph replay sees identical initial state.
__device__ double g_loss_sum;
__device__ double g_cnt;

__global__ __launch_bounds__(THREADS, 8) void sl_main_kernel(
    const float4* __restrict__ emb4,   // [K, B, 32] as float4
    const int*    __restrict__ target, // [K, B]
    int B)
{
    const int warp_in_block = threadIdx.x >> 5;
    const int lane = threadIdx.x & 31;
    const int b = blockIdx.x * WARPS_PER_BLOCK + warp_in_block;

    float loss = 0.0f;
    float inc  = 0.0f;

    if (b < B) {
        const size_t row = (size_t)b * 32 + lane;
        const size_t stream_stride = (size_t)B * 32;

        // Anchor chunk + all 7 peer chunks; streaming (evict-first) loads —
        // this data is touched exactly once.
        float4 a = __ldcs(&emb4[row]);
        float4 e[KSTREAMS - 1];
        #pragma unroll
        for (int k = 1; k < KSTREAMS; k++) {
            e[k - 1] = __ldcs(&emb4[row + (size_t)k * stream_stride]);
        }

        float d[KSTREAMS - 1];
        #pragma unroll
        for (int k = 0; k < KSTREAMS - 1; k++) {
            float dx = a.x - e[k].x;
            float dy = a.y - e[k].y;
            float dz = a.z - e[k].z;
            float dw = a.w - e[k].w;
            d[k] = dx * dx + dy * dy + dz * dz + dw * dw;
        }

        // 7 simultaneous warp butterfly reductions
        #pragma unroll
        for (int off = 16; off > 0; off >>= 1) {
            #pragma unroll
            for (int k = 0; k < KSTREAMS - 1; k++) {
                d[k] += __shfl_xor_sync(0xffffffffu, d[k], off);
            }
        }

        // Targets: lane k (k < 8) loads target[k, b]; broadcast via shfl
        int t = 0;
        if (lane < KSTREAMS) t = target[(size_t)lane * B + b];
        const int t0 = __shfl_sync(0xffffffffu, t, 0);

        bool  same[KSTREAMS - 1];
        bool  any_same = false;
        float mmax = -INFINITY;
        float same_sum = 0.0f;
        #pragma unroll
        for (int k = 1; k < KSTREAMS; k++) {
            int tk = __shfl_sync(0xffffffffu, t, k);
            bool s = (tk == t0);
            same[k - 1] = s;
            if (s) {
                any_same = true;
                mmax = fmaxf(mmax, d[k - 1]);
                same_sum += d[k - 1];
            }
        }

        const float alpha = any_same ? mmax : 1.0f;

        float neg_sum = 0.0f;
        bool  any_neg = false;
        #pragma unroll
        for (int k = 0; k < KSTREAMS - 1; k++) {
            float margin = d[k] - alpha;
            if (!same[k] && margin < 0.0f) {
                neg_sum += margin;
                any_neg = true;
            }
        }

        const bool include = any_same || any_neg;
        loss = include ? (same_sum - neg_sum) : 0.0f;
        inc  = include ? 1.0f : 0.0f;
    }

    // Block reduction of per-warp (lane-0) values
    __shared__ float s_loss[WARPS_PER_BLOCK];
    __shared__ float s_inc[WARPS_PER_BLOCK];
    if (lane == 0) {
        s_loss[warp_in_block] = loss;
        s_inc[warp_in_block]  = inc;
    }
    __syncthreads();

    if (warp_in_block == 0 && lane < WARPS_PER_BLOCK) {
        float vl = s_loss[lane];
        float vi = s_inc[lane];
        #pragma unroll
        for (int off = WARPS_PER_BLOCK / 2; off > 0; off >>= 1) {
            vl += __shfl_xor_sync(0x000000ffu, vl, off);
            vi += __shfl_xor_sync(0x000000ffu, vi, off);
        }
        if (lane == 0) {
            atomicAdd(&g_loss_sum, (double)vl);
            atomicAdd(&g_cnt, (double)vi);
        }
    }

    // PDL trigger: releases the dependent finalize grid's sync once all
    // blocks reach here; prior memory ops are visible to the dependent grid.
    cudaTriggerProgrammaticLaunchCompletion();
}

// Finalize via PDL: launched overlapping the main kernel; the grid-dependency
// sync waits (in hardware) until all primary blocks have triggered and makes
// their writes visible. Consumes totals, writes output, resets accumulators.
__global__ void sl_finalize_kernel(float* __restrict__ out) {
    cudaGridDependencySynchronize();
    double total = g_loss_sum;
    double cnt   = g_cnt;
    if (cnt < 1.0) cnt = 1.0;
    out[0] = (float)(total / cnt);
    g_loss_sum = 0.0;
    g_cnt      = 0.0;
}

extern "C" void kernel_launch(void* const* d_in, const int* in_sizes, int n_in,
                              void* d_out, int out_size) {
    const float* embeddings = (const float*)d_in[0];  // [K, B, D] f32
    const int*   target     = (const int*)d_in[1];    // [K, B] i32
    float* out = (float*)d_out;

    const int B = in_sizes[0] / (KSTREAMS * DDIM);
    const int grid = (B + WARPS_PER_BLOCK - 1) / WARPS_PER_BLOCK;

    sl_main_kernel<<<grid, THREADS>>>((const float4*)embeddings, target, B);

    // PDL launch of finalize: overlaps its launch latency with the main kernel.
    cudaLaunchConfig_t cfg = {};
    cfg.gridDim  = dim3(1, 1, 1);
    cfg.blockDim = dim3(1, 1, 1);
    cfg.dynamicSmemBytes = 0;
    cfg.stream = 0;  // legacy default stream (the capture stream)
    cudaLaunchAttribute attrs[1];
    attrs[0].id = cudaLaunchAttributeProgrammaticStreamSerialization;
    attrs[0].val.programmaticStreamSerializationAllowed = 1;
    cfg.attrs = attrs;
    cfg.numAttrs = 1;
    cudaLaunchKernelEx(&cfg, sl_finalize_kernel, out);
}